// round 12
// baseline (speedup 1.0000x reference)
#include <cuda_runtime.h>
#include <stdint.h>

// Problem constants
#define BINSD   512
#define BATCH   64
#define NPTS    4096
#define CELLS   (BATCH * BINSD * BINSD)      // 16,777,216 cells
#define FILL_BLOCKS 65536                    // 1 float4 store/thread (R1 shape)
#define HASH_BLOCKS BATCH                    // one dedup block per batch

// smem hash: 8192 slots x uint32 = 32 KB. entry = (cell18 << 13) | tok13,
// tok in 1..4096 (occupied entries are nonzero).
#define HASH_SLOTS 8192
#define HASH_MASK  (HASH_SLOTS - 1)

// Winner scratch, rebuilt every replay (deterministic content; list order may
// vary but cells are unique, so the final output is unique).
static __device__ unsigned int g_wcount[BATCH];
static __device__ float4       g_wlist[BATCH * NPTS];   // {x, y, cell_bits, 0}

// ---------------------------------------------------------------------------
// Kernel 1 (fused): 64 hash blocks at the head dedup each batch's points in
// shared memory and emit a compact winner list to global scratch (they never
// touch `out`, so overlapping with fill is race-free). The remaining 65536
// blocks are the R1-exact fill (one float4/thread — the only store shape
// measured at 67% DRAM). Hash blocks are smem-bound (<2% extra traffic) and
// hide completely under the DRAM-bound fill.
// ---------------------------------------------------------------------------
__global__ void __launch_bounds__(256) fused_fill_hash_kernel(
    float4* __restrict__ out, const float4* __restrict__ pts4) {
    unsigned bid = blockIdx.x;

    if (bid >= HASH_BLOCKS) {
        // ---- fill: one float4 per thread ----
        int idx = (int)(bid - HASH_BLOCKS) * 256 + threadIdx.x;  // 0..CELLS-1
        const float inv = 1.0f / (float)BINSD;
        int j = idx & (BINSD - 1);
        int i = (idx >> 9) & (BINSD - 1);
        out[idx] = make_float4(0.63f, 0.63f, (float)j * inv, (float)i * inv);
        return;
    }

    // ---- hash dedup for batch b ----
    __shared__ unsigned int h[HASH_SLOTS];
    __shared__ unsigned int cnt;
    int b   = bid;
    int tid = threadIdx.x;

    #pragma unroll
    for (int s = 0; s < HASH_SLOTS / 256; s++) h[tid + s * 256] = 0u;
    if (tid == 0) cnt = 0u;
    __syncthreads();

    // insert: 16 points per thread (8 coalesced float4 loads)
    const float4* base4 = pts4 + ((size_t)b << 11);     // 4096 pts = 2048 f4
    #pragma unroll
    for (int g = 0; g < 8; g++) {
        float4 A = base4[tid + g * 256];                // pts 2*(tid+g*256)+{0,1}
        int t0 = (tid + g * 256) * 2;                   // first point index
        float px[2] = {A.x, A.z};
        float py[2] = {A.y, A.w};
        #pragma unroll
        for (int k = 0; k < 2; k++) {
            // delta = 1/512 exactly: x/delta == x*512.0f bit-exactly;
            // truncation matches astype(int32) for non-negative inputs.
            int row = (int)(px[k] * 512.0f);
            int col = (int)(py[k] * 512.0f);
            unsigned int cell = (unsigned int)((row << 9) | col);   // 18 bits
            unsigned int ent  = (cell << 13) | (unsigned int)(t0 + k + 1);
            unsigned int slot = cell & HASH_MASK;
            // open addressing: CAS-claim empty slot, or atomicMax on own key
            // (equal key bits -> max == max token == last write in ref order).
            for (;;) {
                unsigned int cur = h[slot];
                if (cur == 0u) {
                    unsigned int prev = atomicCAS(&h[slot], 0u, ent);
                    if (prev == 0u) break;
                    cur = prev;
                }
                if ((cur >> 13) == cell) { atomicMax(&h[slot], ent); break; }
                slot = (slot + 1) & HASH_MASK;
            }
        }
    }
    __syncthreads();

    // readout: compact winners into the global list
    const float2* base2 = (const float2*)base4;
    #pragma unroll
    for (int s = 0; s < HASH_SLOTS / 256; s++) {
        unsigned int ent = h[tid + s * 256];
        if (ent != 0u) {
            unsigned int cell = ent >> 13;
            unsigned int tok  = ent & 0x1FFFu;
            float2 wp = base2[tok - 1u];                // L1/L2-hot reload
            unsigned int pos = atomicAdd(&cnt, 1u);
            g_wlist[(b << 12) + pos] =
                make_float4(wp.x, wp.y, __uint_as_float(cell), 0.0f);
        }
    }
    __syncthreads();
    if (tid == 0) g_wcount[b] = cnt;
}

// ---------------------------------------------------------------------------
// Kernel 2: writeback. 16 blocks per batch x 256 threads = 1 winner/thread;
// coalesced list read, scattered 16B store into out.
// ---------------------------------------------------------------------------
__global__ void __launch_bounds__(256) writeback_kernel(
    float4* __restrict__ out) {
    int b   = blockIdx.x >> 4;                          // 16 blocks per batch
    int idx = ((blockIdx.x & 15) << 8) + threadIdx.x;   // 0..4095 within batch
    if (idx < (int)g_wcount[b]) {
        float4 e = g_wlist[(b << 12) + idx];
        unsigned int cell = __float_as_uint(e.z);
        out[((size_t)b << 18) + cell] = make_float4(1.0f, 1.0f, e.x, e.y);
    }
}

extern "C" void kernel_launch(void* const* d_in, const int* in_sizes, int n_in,
                              void* d_out, int out_size) {
    const float4* pts4 = (const float4*)d_in[0];  // batch [64, 4096, 2] fp32
    float4* out = (float4*)d_out;                 // [64, 512, 512, 4] fp32

    fused_fill_hash_kernel<<<HASH_BLOCKS + FILL_BLOCKS, 256>>>(out, pts4);
    writeback_kernel<<<BATCH * 16, 256>>>(out);
}

// round 13
// speedup vs baseline: 1.7657x; 1.7657x over previous
#include <cuda_runtime.h>
#include <stdint.h>

// Problem constants
#define BINSD   512
#define BATCH   64
#define NPTS    4096
#define CELLS   (BATCH * BINSD * BINSD)      // 16,777,216 cells
#define FILL_BLOCKS 65536                    // 1 float4 store/thread (R1 shape)

// smem hash: 8192 slots x uint32 = 32 KB. entry = (cell18 << 13) | tok13,
// tok in 1..4096 (occupied entries are nonzero).
#define HASH_SLOTS 8192
#define HASH_MASK  (HASH_SLOTS - 1)

// Winner scratch, fully rebuilt every replay (g_wcount[b] is written
// unconditionally for all b each launch -> no stale state across replays).
static __device__ unsigned int g_wcount[BATCH];
static __device__ float4       g_wlist[BATCH * NPTS];   // {x, y, cell_bits, 0}

// ---------------------------------------------------------------------------
// Fill: R1-exact shape (one float4 store/thread, huge grid, ZERO smem —
// keeping smem out of this kernel is load-bearing: R12 showed a 32KB static
// smem array in the same kernel starves L1 and 2.5x's the store stream).
// ---------------------------------------------------------------------------
__global__ void __launch_bounds__(256) fill_kernel(float4* __restrict__ out) {
    int idx = blockIdx.x * 256 + threadIdx.x;          // 0 .. CELLS-1
    const float inv = 1.0f / (float)BINSD;
    int j = idx & (BINSD - 1);
    int i = (idx >> 9) & (BINSD - 1);
    out[idx] = make_float4(0.63f, 0.63f, (float)j * inv, (float)i * inv);
}

// ---------------------------------------------------------------------------
// Hash dedup: one block per batch; exact last-write-wins via max-token in a
// shared open-addressing hash. Emits a compact winner list to global scratch;
// NEVER touches `out`, so it is race-free to run concurrently with fill.
// ---------------------------------------------------------------------------
__global__ void __launch_bounds__(1024) hash_kernel(
    const float4* __restrict__ pts4) {
    __shared__ unsigned int h[HASH_SLOTS];
    __shared__ unsigned int cnt;

    int b   = blockIdx.x;
    int tid = threadIdx.x;

    #pragma unroll
    for (int s = 0; s < 8; s++) h[tid + s * 1024] = 0u;
    if (tid == 0) cnt = 0u;
    __syncthreads();

    // insert: 4 points per thread (two coalesced float4 loads)
    const float4* base4 = pts4 + ((size_t)b << 11);    // 4096 pts = 2048 f4
    int t0 = tid * 4;
    float4 A = base4[tid * 2];
    float4 B = base4[tid * 2 + 1];
    float px[4] = {A.x, A.z, B.x, B.z};
    float py[4] = {A.y, A.w, B.y, B.w};

    #pragma unroll
    for (int k = 0; k < 4; k++) {
        // delta = 1/512 exactly: x/delta == x*512.0f bit-exactly; truncation
        // matches astype(int32) for non-negative inputs.
        int row = (int)(px[k] * 512.0f);
        int col = (int)(py[k] * 512.0f);
        unsigned int cell = (unsigned int)((row << 9) | col);   // 18 bits
        unsigned int ent  = (cell << 13) | (unsigned int)(t0 + k + 1);
        unsigned int slot = cell & HASH_MASK;
        // CAS-claim empty slot, or atomicMax on own key (equal key bits ->
        // max == max token == last write in reference order).
        for (;;) {
            unsigned int cur = h[slot];
            if (cur == 0u) {
                unsigned int prev = atomicCAS(&h[slot], 0u, ent);
                if (prev == 0u) break;
                cur = prev;
            }
            if ((cur >> 13) == cell) { atomicMax(&h[slot], ent); break; }
            slot = (slot + 1) & HASH_MASK;
        }
    }
    __syncthreads();

    // readout: compact winners into the global list
    const float2* base2 = (const float2*)base4;
    #pragma unroll
    for (int s = 0; s < 8; s++) {
        unsigned int ent = h[tid + s * 1024];
        if (ent != 0u) {
            unsigned int cell = ent >> 13;
            unsigned int tok  = ent & 0x1FFFu;
            float2 wp = base2[tok - 1u];               // L1/L2-hot reload
            unsigned int pos = atomicAdd(&cnt, 1u);
            g_wlist[(b << 12) + pos] =
                make_float4(wp.x, wp.y, __uint_as_float(cell), 0.0f);
        }
    }
    __syncthreads();
    if (tid == 0) g_wcount[b] = cnt;
}

// ---------------------------------------------------------------------------
// Writeback: 16 blocks/batch x 256 threads = 1 winner/thread; coalesced list
// read, scattered 16B store into out. Runs after fill AND hash have joined.
// ---------------------------------------------------------------------------
__global__ void __launch_bounds__(256) writeback_kernel(
    float4* __restrict__ out) {
    int b   = blockIdx.x >> 4;
    int idx = ((blockIdx.x & 15) << 8) + threadIdx.x;  // 0..4095 within batch
    if (idx < (int)g_wcount[b]) {
        float4 e = g_wlist[(b << 12) + idx];
        unsigned int cell = __float_as_uint(e.z);
        out[((size_t)b << 18) + cell] = make_float4(1.0f, 1.0f, e.x, e.y);
    }
}

// Host-side stream/event for the parallel branch. Created once on first call
// (host resources only — no device memory). Captured graphs turn the
// event fork/join into parallel graph dependencies.
static cudaStream_t g_hstream = nullptr;
static cudaEvent_t  g_fork = nullptr, g_join = nullptr;

extern "C" void kernel_launch(void* const* d_in, const int* in_sizes, int n_in,
                              void* d_out, int out_size) {
    const float4* pts4 = (const float4*)d_in[0];  // batch [64, 4096, 2] fp32
    float4* out = (float4*)d_out;                 // [64, 512, 512, 4] fp32

    if (g_hstream == nullptr) {
        cudaStreamCreateWithFlags(&g_hstream, cudaStreamNonBlocking);
        cudaEventCreateWithFlags(&g_fork, cudaEventDisableTiming);
        cudaEventCreateWithFlags(&g_join, cudaEventDisableTiming);
    }

    // Fork: hash runs on g_hstream concurrently with fill on the main stream.
    cudaEventRecord(g_fork, 0);
    cudaStreamWaitEvent(g_hstream, g_fork, 0);
    hash_kernel<<<BATCH, 1024, 0, g_hstream>>>(pts4);
    fill_kernel<<<FILL_BLOCKS, 256>>>(out);
    // Join: writeback needs both branches complete.
    cudaEventRecord(g_join, g_hstream);
    cudaStreamWaitEvent(0, g_join, 0);
    writeback_kernel<<<BATCH * 16, 256>>>(out);
}